// round 1
// baseline (speedup 1.0000x reference)
#include <cuda_runtime.h>
#include <math_constants.h>

// Problem: DotProductAttention
//   decoder_hidden  [B=8, Tq=2048, D=1024] fp32
//   encoder_outputs [B=8, Tk=2048, D=1024] fp32
//   scores  = dec @ enc^T           [B, Tq, Tk]
//   weights = softmax(scores, -1)   [B, Tq, Tk]
//   context = weights @ enc         [B, Tq, D]
//   output tuple (context, weights) -> d_out = [context | weights]
//
// Strategy (round 1 baseline): 3 passes.
//   1) gemm_nt: scores written into the weights region of d_out (scratch reuse)
//   2) softmax in-place on that region
//   3) gemm_nn: context written into the context region
// No device allocations; all launches graph-capturable.

#define BM 128
#define BN 128
#define BKK 8
#define TM 8
#define TN 8
// 256 threads = (BN/TN) x (BM/TM) = 16 x 16

// ---------------------------------------------------------------------------
// C[M,N] = A[M,K] * B[N,K]^T   (both row-major, batched via blockIdx.z)
// ---------------------------------------------------------------------------
__global__ __launch_bounds__(256)
void gemm_nt_kernel(const float* __restrict__ A, const float* __restrict__ B,
                    float* __restrict__ C, int M, int N, int K)
{
    __shared__ float As[BKK][BM];
    __shared__ float Bs[BKK][BN];

    const int b = blockIdx.z;
    A += (size_t)b * M * K;
    B += (size_t)b * N * K;
    C += (size_t)b * M * N;

    const int tile_m = blockIdx.y * BM;
    const int tile_n = blockIdx.x * BN;

    const int tid = threadIdx.x;
    const int tx = tid & 15;   // 0..15 -> N direction
    const int ty = tid >> 4;   // 0..15 -> M direction

    // loaders: 128 rows x 8 cols tile, one float4 per thread
    const int lrow = tid >> 1;          // 0..127
    const int lcol = (tid & 1) * 4;     // 0 or 4

    float acc[TM][TN];
#pragma unroll
    for (int i = 0; i < TM; i++)
#pragma unroll
        for (int j = 0; j < TN; j++) acc[i][j] = 0.0f;

    for (int k0 = 0; k0 < K; k0 += BKK) {
        float4 av = *(const float4*)&A[(size_t)(tile_m + lrow) * K + k0 + lcol];
        As[lcol + 0][lrow] = av.x;
        As[lcol + 1][lrow] = av.y;
        As[lcol + 2][lrow] = av.z;
        As[lcol + 3][lrow] = av.w;

        float4 bv = *(const float4*)&B[(size_t)(tile_n + lrow) * K + k0 + lcol];
        Bs[lcol + 0][lrow] = bv.x;
        Bs[lcol + 1][lrow] = bv.y;
        Bs[lcol + 2][lrow] = bv.z;
        Bs[lcol + 3][lrow] = bv.w;

        __syncthreads();

#pragma unroll
        for (int kk = 0; kk < BKK; kk++) {
            float4 a0 = *(const float4*)&As[kk][ty * TM];
            float4 a1 = *(const float4*)&As[kk][ty * TM + 4];
            float4 b0 = *(const float4*)&Bs[kk][tx * TN];
            float4 b1 = *(const float4*)&Bs[kk][tx * TN + 4];
            float a[TM] = {a0.x, a0.y, a0.z, a0.w, a1.x, a1.y, a1.z, a1.w};
            float bb[TN] = {b0.x, b0.y, b0.z, b0.w, b1.x, b1.y, b1.z, b1.w};
#pragma unroll
            for (int i = 0; i < TM; i++)
#pragma unroll
                for (int j = 0; j < TN; j++)
                    acc[i][j] = fmaf(a[i], bb[j], acc[i][j]);
        }
        __syncthreads();
    }

#pragma unroll
    for (int i = 0; i < TM; i++) {
        float* crow = &C[(size_t)(tile_m + ty * TM + i) * N + tile_n + tx * TN];
        ((float4*)crow)[0] = make_float4(acc[i][0], acc[i][1], acc[i][2], acc[i][3]);
        ((float4*)crow)[1] = make_float4(acc[i][4], acc[i][5], acc[i][6], acc[i][7]);
    }
}

// ---------------------------------------------------------------------------
// C[M,N] = A[M,K] * B[K,N]   (row-major, batched via blockIdx.z).
// B batch stride passed explicitly (encoder is [Tk, D] per batch).
// ---------------------------------------------------------------------------
__global__ __launch_bounds__(256)
void gemm_nn_kernel(const float* __restrict__ A, const float* __restrict__ B,
                    float* __restrict__ C, int M, int N, int K)
{
    __shared__ float As[BKK][BM];
    __shared__ float Bs[BKK][BN];

    const int b = blockIdx.z;
    A += (size_t)b * M * K;
    B += (size_t)b * K * N;
    C += (size_t)b * M * N;

    const int tile_m = blockIdx.y * BM;
    const int tile_n = blockIdx.x * BN;

    const int tid = threadIdx.x;
    const int tx = tid & 15;
    const int ty = tid >> 4;

    // A loader: 128 rows x 8 cols
    const int arow = tid >> 1;
    const int acol = (tid & 1) * 4;
    // B loader: 8 rows x 128 cols
    const int brow = tid >> 5;          // 0..7
    const int bcol = (tid & 31) * 4;    // 0..124

    float acc[TM][TN];
#pragma unroll
    for (int i = 0; i < TM; i++)
#pragma unroll
        for (int j = 0; j < TN; j++) acc[i][j] = 0.0f;

    for (int k0 = 0; k0 < K; k0 += BKK) {
        float4 av = *(const float4*)&A[(size_t)(tile_m + arow) * K + k0 + acol];
        As[acol + 0][arow] = av.x;
        As[acol + 1][arow] = av.y;
        As[acol + 2][arow] = av.z;
        As[acol + 3][arow] = av.w;

        float4 bv = *(const float4*)&B[(size_t)(k0 + brow) * N + tile_n + bcol];
        *(float4*)&Bs[brow][bcol] = bv;

        __syncthreads();

#pragma unroll
        for (int kk = 0; kk < BKK; kk++) {
            float4 a0 = *(const float4*)&As[kk][ty * TM];
            float4 a1 = *(const float4*)&As[kk][ty * TM + 4];
            float4 b0 = *(const float4*)&Bs[kk][tx * TN];
            float4 b1 = *(const float4*)&Bs[kk][tx * TN + 4];
            float a[TM] = {a0.x, a0.y, a0.z, a0.w, a1.x, a1.y, a1.z, a1.w};
            float bb[TN] = {b0.x, b0.y, b0.z, b0.w, b1.x, b1.y, b1.z, b1.w};
#pragma unroll
            for (int i = 0; i < TM; i++)
#pragma unroll
                for (int j = 0; j < TN; j++)
                    acc[i][j] = fmaf(a[i], bb[j], acc[i][j]);
        }
        __syncthreads();
    }

#pragma unroll
    for (int i = 0; i < TM; i++) {
        float* crow = &C[(size_t)(tile_m + ty * TM + i) * N + tile_n + tx * TN];
        ((float4*)crow)[0] = make_float4(acc[i][0], acc[i][1], acc[i][2], acc[i][3]);
        ((float4*)crow)[1] = make_float4(acc[i][4], acc[i][5], acc[i][6], acc[i][7]);
    }
}

// ---------------------------------------------------------------------------
// In-place row softmax: one block per row, 256 threads, Tk = 2048 (8/thread)
// ---------------------------------------------------------------------------
__global__ __launch_bounds__(256)
void softmax_rows_kernel(float* __restrict__ W)
{
    const int Tk = 2048;
    float* p = W + (size_t)blockIdx.x * Tk;
    const int tid = threadIdx.x;

    __shared__ float red[8];

    float v[8];
    float m = -CUDART_INF_F;
#pragma unroll
    for (int i = 0; i < 8; i++) {
        v[i] = p[tid + i * 256];
        m = fmaxf(m, v[i]);
    }
#pragma unroll
    for (int o = 16; o; o >>= 1) m = fmaxf(m, __shfl_xor_sync(0xffffffffu, m, o));
    if ((tid & 31) == 0) red[tid >> 5] = m;
    __syncthreads();
    m = red[0];
#pragma unroll
    for (int w = 1; w < 8; w++) m = fmaxf(m, red[w]);
    __syncthreads();

    float s = 0.0f;
#pragma unroll
    for (int i = 0; i < 8; i++) {
        v[i] = __expf(v[i] - m);
        s += v[i];
    }
#pragma unroll
    for (int o = 16; o; o >>= 1) s += __shfl_xor_sync(0xffffffffu, s, o);
    if ((tid & 31) == 0) red[tid >> 5] = s;
    __syncthreads();
    s = red[0];
#pragma unroll
    for (int w = 1; w < 8; w++) s += red[w];
    const float inv = 1.0f / s;

#pragma unroll
    for (int i = 0; i < 8; i++) p[tid + i * 256] = v[i] * inv;
}

// ---------------------------------------------------------------------------
extern "C" void kernel_launch(void* const* d_in, const int* in_sizes, int n_in,
                              void* d_out, int out_size)
{
    const float* dec = (const float*)d_in[0];  // [8, 2048, 1024]
    const float* enc = (const float*)d_in[1];  // [8, 2048, 1024]

    const int B = 8, Tq = 2048, Tk = 2048, D = 1024;

    float* ctx = (float*)d_out;                          // [B, Tq, D]
    float* wts = (float*)d_out + (size_t)B * Tq * D;     // [B, Tq, Tk]

    // 1) scores = dec @ enc^T  -> wts region (raw scores)
    gemm_nt_kernel<<<dim3(Tk / BN, Tq / BM, B), 256>>>(dec, enc, wts, Tq, Tk, D);

    // 2) softmax in place
    softmax_rows_kernel<<<B * Tq, 256>>>(wts);

    // 3) context = wts @ enc
    gemm_nn_kernel<<<dim3(D / BN, Tq / BM, B), 256>>>(wts, enc, ctx, Tq, D, Tk);
}

// round 3
// speedup vs baseline: 2.3955x; 2.3955x over previous
#include <cuda_runtime.h>
#include <cuda_fp16.h>
#include <math_constants.h>
#include <cstdint>

// ============================================================================
// DotProductAttention  (B=8, Tq=Tk=2048, D=1024, fp32)
//   scores  = dec @ enc^T      -> weights region of d_out (scratch reuse)
//   weights = softmax(scores)
//   context = weights @ enc    -> context region
//
// Tensor-core path via generic mma.sync (m16n8k16, f16 in / f32 accum):
// fp32 emulated with fp16 hi/lo 3-term: A*B ~= Ah*Bh + Al*Bh + Ah*Bl.
// (tcgen05 is unavailable: harness PTX target is sm_103 without 'a'.)
// Both GEMMs are NT (A[M,K] * B[N,K]^T); enc is transposed once into scratch
// so GEMM2 (weights @ enc) is also NT.
// ============================================================================

// 64 MB scratch for enc^T  [B=8][D=1024][Tk=2048] fp32
__device__ float g_encT[8u * 1024u * 2048u];

#define BM 128
#define BN 128
#define BK 32
#define LDA 40                      // halfs per smem row (80 B, conflict-free)
#define TILE_HALFS (128 * LDA)      // 5120 halfs per tile
#define STAGE_HALFS (4 * TILE_HALFS)// Ah, Al, Bh, Bl
#define SMEM_BYTES (2 * STAGE_HALFS * 2)  // 81920

// ---------------------------------------------------------------------------
__device__ __forceinline__ uint32_t smem_u32(const void* p) {
    uint32_t a;
    asm("{ .reg .u64 t; cvta.to.shared.u64 t, %1; cvt.u32.u64 %0, t; }"
        : "=r"(a) : "l"(p));
    return a;
}

__device__ __forceinline__ void ldsm_x4(uint32_t& r0, uint32_t& r1,
                                        uint32_t& r2, uint32_t& r3, uint32_t addr) {
    asm volatile("ldmatrix.sync.aligned.m8n8.x4.shared.b16 {%0,%1,%2,%3}, [%4];"
                 : "=r"(r0), "=r"(r1), "=r"(r2), "=r"(r3) : "r"(addr));
}

__device__ __forceinline__ void mma16816(float* c, const uint32_t* a,
                                         uint32_t b0, uint32_t b1) {
    asm volatile(
        "mma.sync.aligned.m16n8k16.row.col.f32.f16.f16.f32 "
        "{%0,%1,%2,%3}, {%4,%5,%6,%7}, {%8,%9}, {%0,%1,%2,%3};"
        : "+f"(c[0]), "+f"(c[1]), "+f"(c[2]), "+f"(c[3])
        : "r"(a[0]), "r"(a[1]), "r"(a[2]), "r"(a[3]), "r"(b0), "r"(b1));
}

// split two fp32 into packed fp16 hi pair and lo (residual) pair
__device__ __forceinline__ void cvt2(float x, float y, uint32_t& hi, uint32_t& lo) {
    __half hx = __float2half_rn(x);
    __half hy = __float2half_rn(y);
    __half lx = __float2half_rn(x - __half2float(hx));
    __half ly = __float2half_rn(y - __half2float(hy));
    hi = (uint32_t)__half_as_ushort(hx) | ((uint32_t)__half_as_ushort(hy) << 16);
    lo = (uint32_t)__half_as_ushort(lx) | ((uint32_t)__half_as_ushort(ly) << 16);
}

// ---------------------------------------------------------------------------
// NT GEMM: C[M,N] = A[M,K] * B[N,K]^T  (fp32, hi/lo fp16 3-term emulation)
// grid = (N/128, M/128, batch), 256 threads (8 warps of 32x64 output)
// ---------------------------------------------------------------------------
__global__ __launch_bounds__(256, 1)
void hmma_gemm_nt(const float* __restrict__ A, const float* __restrict__ Bp,
                  float* __restrict__ C, int M, int N, int K)
{
    extern __shared__ __half sm[];
    const uint32_t smBase = smem_u32(sm);

    const int t    = threadIdx.x;
    const int lane = t & 31;
    const int wid  = t >> 5;
    const int wm   = wid & 3;   // 0..3  (32-row slab)
    const int wn   = wid >> 2;  // 0..1  (64-col slab)

    const int bz = blockIdx.z;
    A  += (size_t)bz * M * K;
    Bp += (size_t)bz * N * K;
    C  += (size_t)bz * M * N;
    const int m0 = blockIdx.y * BM;
    const int n0 = blockIdx.x * BN;

    // ---- gmem loader assignment: per thread, 4 rows (stride 32), 1 float4/row
    const int ldRow = t >> 3;          // 0..31
    const int ldC4  = (t & 7) * 4;     // fp32 column within 32-wide chunk
    const float* aPtr = A + (size_t)(m0 + ldRow) * K + ldC4;
    const float* bPtr = Bp + (size_t)(n0 + ldRow) * K + ldC4;
    const uint32_t stsOff = (uint32_t)(ldRow * LDA + ldC4);  // halfs

    // ---- ldmatrix lane offsets (bytes, relative to tile base)
    const uint32_t aOffB =
        (uint32_t)(((wm * 32 + (lane & 15)) * LDA + (lane >> 4) * 8) * 2);
    const uint32_t bOffB =
        (uint32_t)(((wn * 64 + ((lane >> 4) * 8) + (lane & 7)) * LDA +
                    ((lane >> 3) & 1) * 8) * 2);

    float acc[2][8][4];
#pragma unroll
    for (int i = 0; i < 2; i++)
#pragma unroll
        for (int j = 0; j < 8; j++)
#pragma unroll
            for (int q = 0; q < 4; q++) acc[i][j][q] = 0.0f;

    const int KB = K / BK;

    // ---- prologue: chunk 0 -> stage 0
    {
        float4 av[4], bv[4];
#pragma unroll
        for (int i = 0; i < 4; i++) {
            av[i] = *(const float4*)(aPtr + (size_t)32 * i * K);
            bv[i] = *(const float4*)(bPtr + (size_t)32 * i * K);
        }
        __half* sAh = sm;
        __half* sAl = sm + TILE_HALFS;
        __half* sBh = sm + 2 * TILE_HALFS;
        __half* sBl = sm + 3 * TILE_HALFS;
#pragma unroll
        for (int i = 0; i < 4; i++) {
            uint32_t off = stsOff + i * 32 * LDA;
            uint32_t h0, l0, h1, l1;
            cvt2(av[i].x, av[i].y, h0, l0);
            cvt2(av[i].z, av[i].w, h1, l1);
            *(uint2*)(sAh + off) = make_uint2(h0, h1);
            *(uint2*)(sAl + off) = make_uint2(l0, l1);
            cvt2(bv[i].x, bv[i].y, h0, l0);
            cvt2(bv[i].z, bv[i].w, h1, l1);
            *(uint2*)(sBh + off) = make_uint2(h0, h1);
            *(uint2*)(sBl + off) = make_uint2(l0, l1);
        }
    }
    __syncthreads();

    for (int kb = 0; kb < KB; kb++) {
        const int buf = kb & 1;
        const uint32_t stageB = smBase + (uint32_t)(buf * STAGE_HALFS * 2);

        // issue next chunk's global loads early (latency hidden by compute)
        float4 av[4], bv[4];
        const bool more = (kb + 1 < KB);
        if (more) {
            const float* ap = aPtr + (kb + 1) * BK;
            const float* bp = bPtr + (kb + 1) * BK;
#pragma unroll
            for (int i = 0; i < 4; i++) {
                av[i] = *(const float4*)(ap + (size_t)32 * i * K);
                bv[i] = *(const float4*)(bp + (size_t)32 * i * K);
            }
        }

        // ---- compute on stage `buf`
        const uint32_t tAh = stageB;
        const uint32_t tAl = stageB + TILE_HALFS * 2;
        const uint32_t tBh = stageB + 2 * TILE_HALFS * 2;
        const uint32_t tBl = stageB + 3 * TILE_HALFS * 2;

#pragma unroll
        for (int ks = 0; ks < 2; ks++) {
            uint32_t ah[2][4], al[2][4];
#pragma unroll
            for (int mt = 0; mt < 2; mt++) {
                uint32_t ao = aOffB + (uint32_t)(mt * 16 * LDA * 2 + ks * 32);
                ldsm_x4(ah[mt][0], ah[mt][1], ah[mt][2], ah[mt][3], tAh + ao);
                ldsm_x4(al[mt][0], al[mt][1], al[mt][2], al[mt][3], tAl + ao);
            }
#pragma unroll
            for (int np = 0; np < 4; np++) {
                uint32_t bo = bOffB + (uint32_t)(np * 16 * LDA * 2 + ks * 32);
                uint32_t bh0, bh1, bh2, bh3, bl0, bl1, bl2, bl3;
                ldsm_x4(bh0, bh1, bh2, bh3, tBh + bo);
                ldsm_x4(bl0, bl1, bl2, bl3, tBl + bo);
#pragma unroll
                for (int mt = 0; mt < 2; mt++) {
                    mma16816(acc[mt][2 * np + 0], ah[mt], bh0, bh1);
                    mma16816(acc[mt][2 * np + 1], ah[mt], bh2, bh3);
                    mma16816(acc[mt][2 * np + 0], al[mt], bh0, bh1);
                    mma16816(acc[mt][2 * np + 1], al[mt], bh2, bh3);
                    mma16816(acc[mt][2 * np + 0], ah[mt], bl0, bl1);
                    mma16816(acc[mt][2 * np + 1], ah[mt], bl2, bl3);
                }
            }
        }

        // ---- store next chunk into other stage
        if (more) {
            const int b2 = buf ^ 1;
            __half* sAh = sm + b2 * STAGE_HALFS;
            __half* sAl = sAh + TILE_HALFS;
            __half* sBh = sAh + 2 * TILE_HALFS;
            __half* sBl = sAh + 3 * TILE_HALFS;
#pragma unroll
            for (int i = 0; i < 4; i++) {
                uint32_t off = stsOff + i * 32 * LDA;
                uint32_t h0, l0, h1, l1;
                cvt2(av[i].x, av[i].y, h0, l0);
                cvt2(av[i].z, av[i].w, h1, l1);
                *(uint2*)(sAh + off) = make_uint2(h0, h1);
                *(uint2*)(sAl + off) = make_uint2(l0, l1);
                cvt2(bv[i].x, bv[i].y, h0, l0);
                cvt2(bv[i].z, bv[i].w, h1, l1);
                *(uint2*)(sBh + off) = make_uint2(h0, h1);
                *(uint2*)(sBl + off) = make_uint2(l0, l1);
            }
        }
        __syncthreads();
    }

    // ---- epilogue: write 32x64 per warp
    const int row0 = m0 + wm * 32 + (lane >> 2);
    const int col0 = n0 + wn * 64 + 2 * (lane & 3);
#pragma unroll
    for (int mt = 0; mt < 2; mt++) {
#pragma unroll
        for (int nt = 0; nt < 8; nt++) {
            float* p0 = C + (size_t)(row0 + mt * 16) * N + col0 + nt * 8;
            float* p1 = C + (size_t)(row0 + mt * 16 + 8) * N + col0 + nt * 8;
            *(float2*)p0 = make_float2(acc[mt][nt][0], acc[mt][nt][1]);
            *(float2*)p1 = make_float2(acc[mt][nt][2], acc[mt][nt][3]);
        }
    }
}

// ---------------------------------------------------------------------------
// enc transpose: in [B, Tk, D] -> out [B, D, Tk]
// ---------------------------------------------------------------------------
__global__ __launch_bounds__(256)
void transpose_kernel(const float* __restrict__ in, float* __restrict__ out,
                      int R, int C)
{
    __shared__ float tb[32][33];
    const int bz = blockIdx.z;
    in  += (size_t)bz * R * C;
    out += (size_t)bz * R * C;
    const int c0 = blockIdx.x * 32;
    const int r0 = blockIdx.y * 32;
    const int tx = threadIdx.x & 31;
    const int ty = threadIdx.x >> 5;
#pragma unroll
    for (int j = 0; j < 32; j += 8)
        tb[ty + j][tx] = in[(size_t)(r0 + ty + j) * C + c0 + tx];
    __syncthreads();
#pragma unroll
    for (int j = 0; j < 32; j += 8)
        out[(size_t)(c0 + ty + j) * R + r0 + tx] = tb[tx][ty + j];
}

// ---------------------------------------------------------------------------
// In-place row softmax, Tk = 2048 (8 per thread, 256 threads per row)
// ---------------------------------------------------------------------------
__global__ __launch_bounds__(256)
void softmax_rows_kernel(float* __restrict__ W)
{
    const int Tk = 2048;
    float* p = W + (size_t)blockIdx.x * Tk;
    const int tid = threadIdx.x;

    __shared__ float red[8];

    float v[8];
    float m = -CUDART_INF_F;
#pragma unroll
    for (int i = 0; i < 8; i++) {
        v[i] = p[tid + i * 256];
        m = fmaxf(m, v[i]);
    }
#pragma unroll
    for (int o = 16; o; o >>= 1) m = fmaxf(m, __shfl_xor_sync(0xffffffffu, m, o));
    if ((tid & 31) == 0) red[tid >> 5] = m;
    __syncthreads();
    m = red[0];
#pragma unroll
    for (int w = 1; w < 8; w++) m = fmaxf(m, red[w]);
    __syncthreads();

    float s = 0.0f;
#pragma unroll
    for (int i = 0; i < 8; i++) {
        v[i] = __expf(v[i] - m);
        s += v[i];
    }
#pragma unroll
    for (int o = 16; o; o >>= 1) s += __shfl_xor_sync(0xffffffffu, s, o);
    if ((tid & 31) == 0) red[tid >> 5] = s;
    __syncthreads();
    s = red[0];
#pragma unroll
    for (int w = 1; w < 8; w++) s += red[w];
    const float inv = 1.0f / s;

#pragma unroll
    for (int i = 0; i < 8; i++) p[tid + i * 256] = v[i] * inv;
}

// ---------------------------------------------------------------------------
extern "C" void kernel_launch(void* const* d_in, const int* in_sizes, int n_in,
                              void* d_out, int out_size)
{
    const float* dec = (const float*)d_in[0];  // [8, 2048, 1024]
    const float* enc = (const float*)d_in[1];  // [8, 2048, 1024]

    const int B = 8, Tq = 2048, Tk = 2048, D = 1024;

    float* ctx = (float*)d_out;                          // [B, Tq, D]
    float* wts = (float*)d_out + (size_t)B * Tq * D;     // [B, Tq, Tk]

    float* encT = nullptr;
    cudaGetSymbolAddress((void**)&encT, g_encT);

    cudaFuncSetAttribute(hmma_gemm_nt, cudaFuncAttributeMaxDynamicSharedMemorySize,
                         SMEM_BYTES);

    // 0) encT[b, d, k] = enc[b, k, d]
    transpose_kernel<<<dim3(D / 32, Tk / 32, B), 256>>>(enc, encT, Tk, D);

    // 1) scores = dec @ enc^T  -> wts region
    hmma_gemm_nt<<<dim3(Tk / BN, Tq / BM, B), 256, SMEM_BYTES>>>(
        dec, enc, wts, Tq, Tk, D);

    // 2) softmax in place
    softmax_rows_kernel<<<B * Tq, 256>>>(wts);

    // 3) context = wts @ encT^T  (= wts @ enc)
    hmma_gemm_nt<<<dim3(D / BN, Tq / BM, B), 256, SMEM_BYTES>>>(
        wts, encT, ctx, Tq, D, Tk);
}

// round 4
// speedup vs baseline: 3.4412x; 1.4365x over previous
#include <cuda_runtime.h>
#include <cuda_fp16.h>
#include <math_constants.h>
#include <cstdint>

// ============================================================================
// DotProductAttention (B=8, Tq=Tk=2048, D=1024, fp32)
// fp32-accurate GEMMs on tensor cores via fp16 hi/lo split (mma.sync m16n8k16).
// Round-4: operands pre-split to fp16 in GMEM once; GEMM mainloop is pure
// cp.async -> ldmatrix -> mma, 2-stage pipeline, 2 CTAs/SM.
// GEMM1 (scores): 3 terms (AhBh + AlBh + AhBl). GEMM2 (context): 2 terms.
// ============================================================================

#define NELEM (8u * 2048u * 1024u)        // 16.78M per input tensor
__device__ __half g_decH[NELEM];
__device__ __half g_decL[NELEM];
__device__ __half g_encH[NELEM];
__device__ __half g_encL[NELEM];
__device__ __half g_encTH[NELEM];         // [B, D, Tk]
__device__ __half g_encTL[NELEM];
__device__ __half g_wtsH[8u * 2048u * 2048u];

#define BM 128
#define BN 128
#define BK 32
#define LDA 40                              // halfs per smem row (80B pitch)
#define T_HALFS (128 * LDA)                 // 5120 halfs per tile

// ---------------------------------------------------------------------------
__device__ __forceinline__ uint32_t smem_u32(const void* p) {
    uint32_t a;
    asm("{ .reg .u64 t; cvta.to.shared.u64 t, %1; cvt.u32.u64 %0, t; }"
        : "=r"(a) : "l"(p));
    return a;
}
__device__ __forceinline__ void cp16(uint32_t dst, const void* src) {
    asm volatile("cp.async.cg.shared.global [%0], [%1], 16;"
                 :: "r"(dst), "l"(src) : "memory");
}
__device__ __forceinline__ void cp_commit() {
    asm volatile("cp.async.commit_group;" ::: "memory");
}
template <int N>
__device__ __forceinline__ void cp_wait() {
    asm volatile("cp.async.wait_group %0;" :: "n"(N) : "memory");
}
__device__ __forceinline__ void ldsm_x4(uint32_t& r0, uint32_t& r1,
                                        uint32_t& r2, uint32_t& r3, uint32_t addr) {
    asm volatile("ldmatrix.sync.aligned.m8n8.x4.shared.b16 {%0,%1,%2,%3}, [%4];"
                 : "=r"(r0), "=r"(r1), "=r"(r2), "=r"(r3) : "r"(addr));
}
__device__ __forceinline__ void mma16816(float* c, const uint32_t* a,
                                         uint32_t b0, uint32_t b1) {
    asm volatile(
        "mma.sync.aligned.m16n8k16.row.col.f32.f16.f16.f32 "
        "{%0,%1,%2,%3}, {%4,%5,%6,%7}, {%8,%9}, {%0,%1,%2,%3};"
        : "+f"(c[0]), "+f"(c[1]), "+f"(c[2]), "+f"(c[3])
        : "r"(a[0]), "r"(a[1]), "r"(a[2]), "r"(a[3]), "r"(b0), "r"(b1));
}

// ---------------------------------------------------------------------------
// NT GEMM: C[M,N] = A[M,K] * B[N,K]^T, A/B given as fp16 hi/lo arrays.
// NTERMS=3: AhBh + AlBh + AhBl.  NTERMS=2: AhBh + AhBl (A lo unused).
// grid = (N/128, M/128, batch), 256 threads, 2 CTAs/SM.
// ---------------------------------------------------------------------------
template <int NTERMS>
__global__ __launch_bounds__(256, 2)
void hmma_gemm_nt_f16(const __half* __restrict__ AH, const __half* __restrict__ AL,
                      const __half* __restrict__ BH, const __half* __restrict__ BL,
                      float* __restrict__ C, int M, int N, int K)
{
    constexpr int TILES = NTERMS + 1;               // Ah[,Al],Bh,Bl
    constexpr int STAGE_HALFS = TILES * T_HALFS;
    constexpr uint32_t OFF_AH = 0;
    constexpr uint32_t OFF_AL = T_HALFS;                        // 3-term only
    constexpr uint32_t OFF_BH = (NTERMS - 1) * T_HALFS;
    constexpr uint32_t OFF_BL = NTERMS * T_HALFS;

    extern __shared__ __half sm[];
    const uint32_t smBase = smem_u32(sm);

    const int t    = threadIdx.x;
    const int lane = t & 31;
    const int wid  = t >> 5;
    const int wm   = wid & 3;
    const int wn   = wid >> 2;

    const int bz = blockIdx.z;
    AH += (size_t)bz * M * K;
    BH += (size_t)bz * N * K;
    BL += (size_t)bz * N * K;
    if (NTERMS == 3) AL += (size_t)bz * M * K;
    C += (size_t)bz * M * N;
    const int m0 = blockIdx.y * BM;
    const int n0 = blockIdx.x * BN;

    // loader: 2 chunks of 16B per tile per thread
    const int r0c = t >> 2;             // chunk0 row (0..63)
    const int c0c = t & 3;              // chunk0 col-chunk (0..3)
    const int r1c = r0c + 64;           // chunk1 row
    const uint32_t d0 = (uint32_t)(r0c * LDA + c0c * 8) * 2;   // bytes
    const uint32_t d1 = (uint32_t)(r1c * LDA + c0c * 8) * 2;
    const size_t g0A = (size_t)(m0 + r0c) * K + c0c * 8;
    const size_t g1A = (size_t)(m0 + r1c) * K + c0c * 8;
    const size_t g0B = (size_t)(n0 + r0c) * K + c0c * 8;
    const size_t g1B = (size_t)(n0 + r1c) * K + c0c * 8;

    // ldmatrix lane offsets (bytes, rel. to tile base)
    const uint32_t aOffB =
        (uint32_t)(((wm * 32 + (lane & 15)) * LDA + (lane >> 4) * 8) * 2);
    const uint32_t bOffB =
        (uint32_t)(((wn * 64 + ((lane >> 4) * 8) + (lane & 7)) * LDA +
                    ((lane >> 3) & 1) * 8) * 2);

    float acc[2][8][4];
#pragma unroll
    for (int i = 0; i < 2; i++)
#pragma unroll
        for (int j = 0; j < 8; j++)
#pragma unroll
            for (int q = 0; q < 4; q++) acc[i][j][q] = 0.0f;

    const int KB = K / BK;

    auto issue_stage = [&](int kb, int buf) {
        const uint32_t sb = smBase + (uint32_t)(buf * STAGE_HALFS * 2);
        const int ko = kb * BK;
        cp16(sb + OFF_AH * 2 + d0, AH + g0A + ko);
        cp16(sb + OFF_AH * 2 + d1, AH + g1A + ko);
        if (NTERMS == 3) {
            cp16(sb + OFF_AL * 2 + d0, AL + g0A + ko);
            cp16(sb + OFF_AL * 2 + d1, AL + g1A + ko);
        }
        cp16(sb + OFF_BH * 2 + d0, BH + g0B + ko);
        cp16(sb + OFF_BH * 2 + d1, BH + g1B + ko);
        cp16(sb + OFF_BL * 2 + d0, BL + g0B + ko);
        cp16(sb + OFF_BL * 2 + d1, BL + g1B + ko);
    };

    // prologue: stages 0 and 1
    issue_stage(0, 0); cp_commit();
    issue_stage(1, 1); cp_commit();

    for (int kb = 0; kb < KB; kb++) {
        const int buf = kb & 1;
        cp_wait<1>();
        __syncthreads();

        const uint32_t sb = smBase + (uint32_t)(buf * STAGE_HALFS * 2);
        const uint32_t tAh = sb + OFF_AH * 2;
        const uint32_t tAl = sb + OFF_AL * 2;
        const uint32_t tBh = sb + OFF_BH * 2;
        const uint32_t tBl = sb + OFF_BL * 2;

#pragma unroll
        for (int ks = 0; ks < 2; ks++) {
            uint32_t ah[2][4], al[2][4];
#pragma unroll
            for (int mt = 0; mt < 2; mt++) {
                uint32_t ao = aOffB + (uint32_t)(mt * 16 * LDA * 2 + ks * 32);
                ldsm_x4(ah[mt][0], ah[mt][1], ah[mt][2], ah[mt][3], tAh + ao);
                if (NTERMS == 3)
                    ldsm_x4(al[mt][0], al[mt][1], al[mt][2], al[mt][3], tAl + ao);
            }
#pragma unroll
            for (int np = 0; np < 4; np++) {
                uint32_t bo = bOffB + (uint32_t)(np * 16 * LDA * 2 + ks * 32);
                uint32_t bh0, bh1, bh2, bh3, bl0, bl1, bl2, bl3;
                ldsm_x4(bh0, bh1, bh2, bh3, tBh + bo);
                ldsm_x4(bl0, bl1, bl2, bl3, tBl + bo);
#pragma unroll
                for (int mt = 0; mt < 2; mt++) {
                    mma16816(acc[mt][2 * np + 0], ah[mt], bh0, bh1);
                    mma16816(acc[mt][2 * np + 1], ah[mt], bh2, bh3);
                    if (NTERMS == 3) {
                        mma16816(acc[mt][2 * np + 0], al[mt], bh0, bh1);
                        mma16816(acc[mt][2 * np + 1], al[mt], bh2, bh3);
                    }
                    mma16816(acc[mt][2 * np + 0], ah[mt], bl0, bl1);
                    mma16816(acc[mt][2 * np + 1], ah[mt], bl2, bl3);
                }
            }
        }

        __syncthreads();                 // all warps done reading stage `buf`
        if (kb + 2 < KB) issue_stage(kb + 2, buf);
        cp_commit();                     // keep group accounting aligned
    }

    // epilogue: 32x64 per warp
    const int row0 = m0 + wm * 32 + (lane >> 2);
    const int col0 = n0 + wn * 64 + 2 * (lane & 3);
#pragma unroll
    for (int mt = 0; mt < 2; mt++) {
#pragma unroll
        for (int nt = 0; nt < 8; nt++) {
            float* p0 = C + (size_t)(row0 + mt * 16) * N + col0 + nt * 8;
            float* p1 = C + (size_t)(row0 + mt * 16 + 8) * N + col0 + nt * 8;
            *(float2*)p0 = make_float2(acc[mt][nt][0], acc[mt][nt][1]);
            *(float2*)p1 = make_float2(acc[mt][nt][2], acc[mt][nt][3]);
        }
    }
}

// ---------------------------------------------------------------------------
// elementwise fp32 -> fp16 hi/lo split
// ---------------------------------------------------------------------------
__global__ __launch_bounds__(256)
void split_kernel(const float* __restrict__ in, __half* __restrict__ hi,
                  __half* __restrict__ lo, unsigned n4)
{
    unsigned i = blockIdx.x * 256u + threadIdx.x;
    if (i >= n4) return;
    float4 v = ((const float4*)in)[i];
    __half h0 = __float2half_rn(v.x), h1 = __float2half_rn(v.y);
    __half h2 = __float2half_rn(v.z), h3 = __float2half_rn(v.w);
    __half l0 = __float2half_rn(v.x - __half2float(h0));
    __half l1 = __float2half_rn(v.y - __half2float(h1));
    __half l2 = __float2half_rn(v.z - __half2float(h2));
    __half l3 = __float2half_rn(v.w - __half2float(h3));
    uint2 hp, lp;
    hp.x = (uint32_t)__half_as_ushort(h0) | ((uint32_t)__half_as_ushort(h1) << 16);
    hp.y = (uint32_t)__half_as_ushort(h2) | ((uint32_t)__half_as_ushort(h3) << 16);
    lp.x = (uint32_t)__half_as_ushort(l0) | ((uint32_t)__half_as_ushort(l1) << 16);
    lp.y = (uint32_t)__half_as_ushort(l2) | ((uint32_t)__half_as_ushort(l3) << 16);
    ((uint2*)hi)[i] = hp;
    ((uint2*)lo)[i] = lp;
}

// ---------------------------------------------------------------------------
// transpose + split: in [B, R, C] fp32 -> outH/outL [B, C, R] fp16
// ---------------------------------------------------------------------------
__global__ __launch_bounds__(256)
void transpose_split_kernel(const float* __restrict__ in,
                            __half* __restrict__ outH, __half* __restrict__ outL,
                            int R, int C)
{
    __shared__ float tb[32][33];
    const int bz = blockIdx.z;
    in += (size_t)bz * R * C;
    const size_t ob = (size_t)bz * R * C;
    const int c0 = blockIdx.x * 32;
    const int r0 = blockIdx.y * 32;
    const int tx = threadIdx.x & 31;
    const int ty = threadIdx.x >> 5;
#pragma unroll
    for (int j = 0; j < 32; j += 8)
        tb[ty + j][tx] = in[(size_t)(r0 + ty + j) * C + c0 + tx];
    __syncthreads();
#pragma unroll
    for (int j = 0; j < 32; j += 8) {
        float v = tb[tx][ty + j];
        __half h = __float2half_rn(v);
        __half l = __float2half_rn(v - __half2float(h));
        size_t o = ob + (size_t)(c0 + ty + j) * R + r0 + tx;
        outH[o] = h;
        outL[o] = l;
    }
}

// ---------------------------------------------------------------------------
// In-place row softmax + fp16 copy of the weights, Tk = 2048
// ---------------------------------------------------------------------------
__global__ __launch_bounds__(256)
void softmax_rows_kernel(float* __restrict__ W, __half* __restrict__ WH)
{
    const int Tk = 2048;
    const size_t base = (size_t)blockIdx.x * Tk;
    float* p = W + base;
    __half* ph = WH + base;
    const int tid = threadIdx.x;

    __shared__ float red[8];

    float v[8];
    float m = -CUDART_INF_F;
#pragma unroll
    for (int i = 0; i < 8; i++) {
        v[i] = p[tid + i * 256];
        m = fmaxf(m, v[i]);
    }
#pragma unroll
    for (int o = 16; o; o >>= 1) m = fmaxf(m, __shfl_xor_sync(0xffffffffu, m, o));
    if ((tid & 31) == 0) red[tid >> 5] = m;
    __syncthreads();
    m = red[0];
#pragma unroll
    for (int w = 1; w < 8; w++) m = fmaxf(m, red[w]);
    __syncthreads();

    float s = 0.0f;
#pragma unroll
    for (int i = 0; i < 8; i++) {
        v[i] = __expf(v[i] - m);
        s += v[i];
    }
#pragma unroll
    for (int o = 16; o; o >>= 1) s += __shfl_xor_sync(0xffffffffu, s, o);
    if ((tid & 31) == 0) red[tid >> 5] = s;
    __syncthreads();
    s = red[0];
#pragma unroll
    for (int w = 1; w < 8; w++) s += red[w];
    const float inv = 1.0f / s;

#pragma unroll
    for (int i = 0; i < 8; i++) {
        float w = v[i] * inv;
        p[tid + i * 256] = w;
        ph[tid + i * 256] = __float2half_rn(w);
    }
}

// ---------------------------------------------------------------------------
extern "C" void kernel_launch(void* const* d_in, const int* in_sizes, int n_in,
                              void* d_out, int out_size)
{
    const float* dec = (const float*)d_in[0];  // [8, 2048, 1024]
    const float* enc = (const float*)d_in[1];  // [8, 2048, 1024]

    const int B = 8, Tq = 2048, Tk = 2048, D = 1024;

    float* ctx = (float*)d_out;                          // [B, Tq, D]
    float* wts = (float*)d_out + (size_t)B * Tq * D;     // [B, Tq, Tk]

    __half *decH, *decL, *encH, *encL, *encTH, *encTL, *wtsH;
    cudaGetSymbolAddress((void**)&decH, g_decH);
    cudaGetSymbolAddress((void**)&decL, g_decL);
    cudaGetSymbolAddress((void**)&encH, g_encH);
    cudaGetSymbolAddress((void**)&encL, g_encL);
    cudaGetSymbolAddress((void**)&encTH, g_encTH);
    cudaGetSymbolAddress((void**)&encTL, g_encTL);
    cudaGetSymbolAddress((void**)&wtsH, g_wtsH);

    constexpr int SMEM3 = 2 * 4 * T_HALFS * 2;   // 81920
    constexpr int SMEM2 = 2 * 3 * T_HALFS * 2;   // 61440
    cudaFuncSetAttribute(hmma_gemm_nt_f16<3>,
                         cudaFuncAttributeMaxDynamicSharedMemorySize, SMEM3);
    cudaFuncSetAttribute(hmma_gemm_nt_f16<2>,
                         cudaFuncAttributeMaxDynamicSharedMemorySize, SMEM2);

    const unsigned n4 = NELEM / 4;

    // 0) pre-split operands
    split_kernel<<<(n4 + 255) / 256, 256>>>(dec, decH, decL, n4);
    split_kernel<<<(n4 + 255) / 256, 256>>>(enc, encH, encL, n4);
    transpose_split_kernel<<<dim3(D / 32, Tk / 32, B), 256>>>(enc, encTH, encTL, Tk, D);

    // 1) scores = dec @ enc^T  (3-term)
    hmma_gemm_nt_f16<3><<<dim3(Tk / BN, Tq / BM, B), 256, SMEM3>>>(
        decH, decL, encH, encL, wts, Tq, Tk, D);

    // 2) softmax in place (+ fp16 weights)
    softmax_rows_kernel<<<B * Tq, 256>>>(wts, wtsH);

    // 3) context = weights @ enc  (2-term, A = wtsH)
    hmma_gemm_nt_f16<2><<<dim3(D / BN, Tq / BM, B), 256, SMEM2>>>(
        wtsH, nullptr, encTH, encTL, ctx, Tq, D, Tk);
}